// round 9
// baseline (speedup 1.0000x reference)
#include <cuda_runtime.h>
#include <cuda_fp16.h>
#include <cstdint>

#define NR 8192
#define MC 8192
#define DD 64

// ---------------- device-global staging (no allocation allowed) ----------------
__device__ __align__(16) __half g_ah[NR * DD];
__device__ __align__(16) __half g_al[NR * DD];
__device__ __align__(16) __half g_bh[MC * DD];
__device__ __align__(16) __half g_bl[MC * DD];
__device__ float2 g_apa[NR];   // a-rows: {|a|^2, 2/(1-|a|^2)}
__device__ float2 g_bq[MC];    // b-rows: {|b|^2, 1/(1-|b|^2)}

// ---------------- helpers ----------------
__device__ __forceinline__ float fast_sqrt(float x) {
    float r; asm("sqrt.approx.f32 %0, %1;" : "=f"(r) : "f"(x)); return r;
}
__device__ __forceinline__ uint32_t smem_u32(const void* p) {
    uint32_t a;
    asm("{ .reg .u64 t; cvta.to.shared.u64 t, %1; cvt.u32.u64 %0, t; }" : "=r"(a) : "l"(p));
    return a;
}
#define CP_ASYNC16(dst, src) \
    asm volatile("cp.async.cg.shared.global [%0], [%1], 16;" :: "r"(dst), "l"(src) : "memory")
#define CP_COMMIT() asm volatile("cp.async.commit_group;" ::: "memory")
#define CP_WAIT0()  asm volatile("cp.async.wait_group 0;" ::: "memory")

#define LDSM4(R, a) \
    asm volatile("ldmatrix.sync.aligned.m8n8.x4.shared.b16 {%0,%1,%2,%3}, [%4];" \
        : "=r"((R)[0]), "=r"((R)[1]), "=r"((R)[2]), "=r"((R)[3]) : "r"(a))

#define MMA16816(d, a, b0, b1) \
    asm volatile("mma.sync.aligned.m16n8k16.row.col.f32.f16.f16.f32 " \
        "{%0,%1,%2,%3}, {%4,%5,%6,%7}, {%8,%9}, {%0,%1,%2,%3};" \
        : "+f"((d)[0]), "+f"((d)[1]), "+f"((d)[2]), "+f"((d)[3]) \
        : "r"((a)[0]), "r"((a)[1]), "r"((a)[2]), "r"((a)[3]), "r"(b0), "r"(b1))

#define BAR_SYNC(id, cnt)   asm volatile("bar.sync %0, %1;"   :: "r"(id), "r"(cnt) : "memory")
#define BAR_ARRIVE(id, cnt) asm volatile("bar.arrive %0, %1;" :: "r"(id), "r"(cnt) : "memory")

// ---------------- prep: norms + reciprocal terms + fp16 hi/lo split ----------------
__global__ void poincare_prep_kernel(const float* __restrict__ a,
                                     const float* __restrict__ b) {
    int warp = (blockIdx.x * blockDim.x + threadIdx.x) >> 5;
    int lane = threadIdx.x & 31;
    const float* row;
    __half *dh, *dl;
    bool isA = warp < NR;
    int r = isA ? warp : warp - NR;
    if (isA) { row = a + (size_t)r * DD; dh = g_ah + (size_t)r * DD; dl = g_al + (size_t)r * DD; }
    else     { row = b + (size_t)r * DD; dh = g_bh + (size_t)r * DD; dl = g_bl + (size_t)r * DD; }

    float v0 = row[lane], v1 = row[lane + 32];
    __half h0 = __float2half_rn(v0);
    __half l0 = __float2half_rn(v0 - __half2float(h0));
    __half h1 = __float2half_rn(v1);
    __half l1 = __float2half_rn(v1 - __half2float(h1));
    dh[lane] = h0;  dh[lane + 32] = h1;
    dl[lane] = l0;  dl[lane + 32] = l1;

    float s = fmaf(v0, v0, v1 * v1);
    #pragma unroll
    for (int o = 16; o > 0; o >>= 1) s += __shfl_xor_sync(0xffffffffu, s, o);
    if (lane == 0) {
        if (isA) g_apa[r] = make_float2(s, 2.0f / (1.0f - s));
        else     g_bq[r]  = make_float2(s, 1.0f / (1.0f - s));
    }
}

// ---------------- main: warp-specialized producer/consumer ----------------
// 512 threads: warps 0-7 = MMA producers, warps 8-15 = epilogue consumers.
// Producers: LDSM + 3-pass fp16-split HMMA, STS raw dots to double-buffered smem.
// Consumers: LDS.128 dots -> Poincare epilogue -> coalesced STG.128.
// Named barriers: 1+s = "dots full(s)", 3+s = "dots empty(s)", 5 = producer-only.
#define PITCH 144
#define BH_BYTES (128 * PITCH)            // 18432
#define A_HALF   (64 * PITCH)             // 9216
#define A_BUF    (2 * A_HALF)             // 18432
#define OFF_B    0
#define OFF_A    (2 * BH_BYTES)           // 36864
#define DOT_PITCH_F 136                   // floats per row (bank-conflict-free)
#define DOT_ROW_B   (DOT_PITCH_F * 4)     // 544
#define DOT_BUF     (64 * DOT_ROW_B)      // 34816
#define OFF_DOT  (OFF_A + 2 * A_BUF)      // 73728
#define SMEM_TOTAL (OFF_DOT + 2 * DOT_BUF)  // 143360 -> 1 CTA/SM

#define TILES 64

__global__ void __launch_bounds__(512, 1)
poincare_ws_kernel(float* __restrict__ out) {
    extern __shared__ char smem[];
    const uint32_t sb = smem_u32(smem);

    const int tid  = threadIdx.x;
    const int lane = tid & 31;
    const int wid  = tid >> 5;

    const int band  = blockIdx.x & 63;
    const int half  = blockIdx.x >> 6;          // 0..1
    const int col0  = band * 128;
    const int rbase = half * 4096;               // a-row base for this CTA

    if (wid < 8) {
        // ================= PRODUCERS (warps 0-7) =================
        const int wm = wid >> 2;        // 0..1
        const int wn = wid & 3;         // 0..3

        // load B band (hi+lo) once + A tile 0
        #pragma unroll
        for (int t = 0; t < 4; t++) {
            int chunk = tid + 256 * t;           // 0..1023
            int r = chunk >> 3;
            int kc = chunk & 7;
            uint32_t doff = (uint32_t)(r * PITCH + kc * 16);
            CP_ASYNC16(sb + OFF_B + doff,            g_bh + (size_t)(col0 + r) * DD + kc * 8);
            CP_ASYNC16(sb + OFF_B + BH_BYTES + doff, g_bl + (size_t)(col0 + r) * DD + kc * 8);
        }
        #pragma unroll
        for (int t = 0; t < 2; t++) {
            int chunk = tid + 256 * t;           // 0..511
            int r = chunk >> 3;
            int kc = chunk & 7;
            uint32_t doff = (uint32_t)(r * PITCH + kc * 16);
            CP_ASYNC16(sb + OFF_A + doff,          g_ah + (size_t)(rbase + r) * DD + kc * 8);
            CP_ASYNC16(sb + OFF_A + A_HALF + doff, g_al + (size_t)(rbase + r) * DD + kc * 8);
        }
        CP_COMMIT();

        const uint32_t a_row  = (uint32_t)(wm * 32 + (lane & 15));
        const uint32_t a_koff = (uint32_t)((lane >> 4) * 16);
        const uint32_t b_row  = (uint32_t)(wn * 32 + ((lane & 16) >> 1) + (lane & 7));
        const uint32_t b_koff = (uint32_t)(((lane >> 3) & 1) * 16);
        const uint32_t uBh = sb + OFF_B;
        const uint32_t uBl = sb + OFF_B + BH_BYTES;

        // dot STS base for this warp's fragments
        const int frow = wm * 32 + (lane >> 2);
        const int fcol = wn * 32 + 2 * (lane & 3);

        for (int it = 0; it < TILES; it++) {
            const int s = it & 1;

            CP_WAIT0();
            BAR_SYNC(5, 256);                     // A tile `it` visible to all producers

            // prefetch next A tile (other buffer; safe: all producers past its reads)
            if (it + 1 < TILES) {
                int nrow = rbase + (it + 1) * 64;
                uint32_t abase = sb + OFF_A + ((it + 1) & 1) * A_BUF;
                #pragma unroll
                for (int t = 0; t < 2; t++) {
                    int chunk = tid + 256 * t;
                    int r = chunk >> 3;
                    int kc = chunk & 7;
                    uint32_t doff = (uint32_t)(r * PITCH + kc * 16);
                    CP_ASYNC16(abase + doff,          g_ah + (size_t)(nrow + r) * DD + kc * 8);
                    CP_ASYNC16(abase + A_HALF + doff, g_al + (size_t)(nrow + r) * DD + kc * 8);
                }
                CP_COMMIT();
            }

            // ---- MMA over K=64 (overlaps consumers' epilogue of tile it-1) ----
            float acc[2][4][4];
            #pragma unroll
            for (int i = 0; i < 2; i++)
                #pragma unroll
                for (int j = 0; j < 4; j++)
                    #pragma unroll
                    for (int q = 0; q < 4; q++) acc[i][j][q] = 0.0f;

            const uint32_t uAh = sb + OFF_A + (it & 1) * A_BUF;
            const uint32_t uAl = uAh + A_HALF;

            #pragma unroll
            for (int ks = 0; ks < 4; ks++) {
                const uint32_t kb = (uint32_t)(ks * 32);
                uint32_t Ah[2][4], Al[2][4];
                #pragma unroll
                for (int mf = 0; mf < 2; mf++) {
                    uint32_t off = (a_row + mf * 16) * PITCH + kb + a_koff;
                    LDSM4(Ah[mf], uAh + off);
                    LDSM4(Al[mf], uAl + off);
                }
                uint32_t Bh[2][4], Bl[2][4];
                #pragma unroll
                for (int nh = 0; nh < 2; nh++) {
                    uint32_t off = (b_row + nh * 16) * PITCH + kb + b_koff;
                    LDSM4(Bh[nh], uBh + off);
                    LDSM4(Bl[nh], uBl + off);
                }
                #pragma unroll
                for (int nf = 0; nf < 4; nf++) {
                    uint32_t bh0 = Bh[nf >> 1][(nf & 1) * 2], bh1 = Bh[nf >> 1][(nf & 1) * 2 + 1];
                    uint32_t bl0 = Bl[nf >> 1][(nf & 1) * 2], bl1 = Bl[nf >> 1][(nf & 1) * 2 + 1];
                    #pragma unroll
                    for (int mf = 0; mf < 2; mf++) {
                        MMA16816(acc[mf][nf], Ah[mf], bh0, bh1);   // hi*hi
                        MMA16816(acc[mf][nf], Ah[mf], bl0, bl1);   // hi*lo
                        MMA16816(acc[mf][nf], Al[mf], bh0, bh1);   // lo*hi
                    }
                }
            }

            // ---- wait dot buffer s free, then STS dots ----
            if (it >= 2) BAR_SYNC(3 + s, 512);

            char* dbase = smem + OFF_DOT + s * DOT_BUF;
            #pragma unroll
            for (int mf = 0; mf < 2; mf++)
                #pragma unroll
                for (int qh = 0; qh < 2; qh++) {
                    int r = frow + mf * 16 + qh * 8;
                    #pragma unroll
                    for (int nf = 0; nf < 4; nf++) {
                        *reinterpret_cast<float2*>(dbase + r * DOT_ROW_B + (fcol + nf * 8) * 4) =
                            make_float2(acc[mf][nf][2 * qh], acc[mf][nf][2 * qh + 1]);
                    }
                }

            BAR_ARRIVE(1 + s, 512);               // dots(s) full
        }
    } else {
        // ================= CONSUMERS (warps 8-15) =================
        const int wc = wid - 8;                   // 0..7 -> rows wc*8..wc*8+7
        // column stats: fixed per lane for whole kernel
        float2 cb[4];
        #pragma unroll
        for (int j = 0; j < 4; j++)
            cb[j] = __ldg(&g_bq[col0 + 4 * lane + j]);

        for (int it = 0; it < TILES; it++) {
            const int s = it & 1;
            const int row0 = rbase + it * 64;

            // row stats (broadcast loads; issue before barrier-protected reads)
            float2 rsv[8];
            #pragma unroll
            for (int rr = 0; rr < 8; rr++)
                rsv[rr] = __ldg(&g_apa[row0 + wc * 8 + rr]);

            BAR_SYNC(1 + s, 512);                 // wait dots(s) full

            char* dbase = smem + OFF_DOT + s * DOT_BUF;
            #pragma unroll
            for (int rr = 0; rr < 8; rr++) {
                float4 dv = *reinterpret_cast<const float4*>(
                    dbase + (wc * 8 + rr) * DOT_ROW_B + lane * 16);
                float2 ra = rsv[rr];
                float res[4];
                const float* dp = &dv.x;
                #pragma unroll
                for (int j = 0; j < 4; j++) {
                    float c  = ra.y * cb[j].y;
                    float sq = fmaf(-2.0f, dp[j], ra.x + cb[j].x);
                    sq = fmaxf(sq, 0.0f);
                    float y2 = (sq * c) * c;
                    float y  = fast_sqrt(sq) * c;
                    float tt = fmaf(2.0f, y, y2);
                    res[j] = __logf(1.0f + y + fast_sqrt(tt));
                }
                *reinterpret_cast<float4*>(
                    out + (size_t)(row0 + wc * 8 + rr) * MC + col0 + 4 * lane) =
                    make_float4(res[0], res[1], res[2], res[3]);
            }

            BAR_ARRIVE(3 + s, 512);               // dots(s) empty
        }
    }
}

extern "C" void kernel_launch(void* const* d_in, const int* in_sizes, int n_in,
                              void* d_out, int out_size) {
    const float* a = (const float*)d_in[0];
    const float* b = (const float*)d_in[1];
    float* out = (float*)d_out;

    cudaFuncSetAttribute(poincare_ws_kernel,
                         cudaFuncAttributeMaxDynamicSharedMemorySize, SMEM_TOTAL);

    poincare_prep_kernel<<<(NR + MC) / 8, 256>>>(a, b);
    poincare_ws_kernel<<<128, 512, SMEM_TOTAL>>>(out);
}

// round 11
// speedup vs baseline: 1.2471x; 1.2471x over previous
#include <cuda_runtime.h>
#include <cuda_fp16.h>
#include <cstdint>

#define NR 8192
#define MC 8192
#define DD 64

// ---------------- device-global staging (no allocation allowed) ----------------
__device__ __align__(16) __half g_ah[NR * DD];          // A: hi only (2-pass split)
__device__ __align__(16) __half g_bh[MC * DD];          // B: hi
__device__ __align__(16) __half g_bl[MC * DD];          // B: lo (residual)
// stats: x = |p|^2 ; y = SQUARED reciprocal term: (2/(1-a2))^2 resp. (1/(1-b2))^2
__device__ float2 g_apa[NR];
__device__ float2 g_bq[MC];

// ---------------- helpers ----------------
__device__ __forceinline__ float fast_sqrt(float x) {
    float r; asm("sqrt.approx.f32 %0, %1;" : "=f"(r) : "f"(x)); return r;
}
__device__ __forceinline__ uint32_t smem_u32(const void* p) {
    uint32_t a;
    asm("{ .reg .u64 t; cvta.to.shared.u64 t, %1; cvt.u32.u64 %0, t; }" : "=r"(a) : "l"(p));
    return a;
}
#define CP_ASYNC16(dst, src) \
    asm volatile("cp.async.cg.shared.global [%0], [%1], 16;" :: "r"(dst), "l"(src) : "memory")
#define CP_COMMIT() asm volatile("cp.async.commit_group;" ::: "memory")
#define CP_WAIT0()  asm volatile("cp.async.wait_group 0;" ::: "memory")

#define LDSM4(R, a) \
    asm volatile("ldmatrix.sync.aligned.m8n8.x4.shared.b16 {%0,%1,%2,%3}, [%4];" \
        : "=r"((R)[0]), "=r"((R)[1]), "=r"((R)[2]), "=r"((R)[3]) : "r"(a))

#define MMA16816(d, a, b0, b1) \
    asm volatile("mma.sync.aligned.m16n8k16.row.col.f32.f16.f16.f32 " \
        "{%0,%1,%2,%3}, {%4,%5,%6,%7}, {%8,%9}, {%0,%1,%2,%3};" \
        : "+f"((d)[0]), "+f"((d)[1]), "+f"((d)[2]), "+f"((d)[3]) \
        : "r"((a)[0]), "r"((a)[1]), "r"((a)[2]), "r"((a)[3]), "r"(b0), "r"(b1))

// ---------------- prep: norms + SQUARED reciprocal terms + fp16 split ----------------
__global__ void poincare_prep_kernel(const float* __restrict__ a,
                                     const float* __restrict__ b) {
    int warp = (blockIdx.x * blockDim.x + threadIdx.x) >> 5;
    int lane = threadIdx.x & 31;
    bool isA = warp < NR;
    int r = isA ? warp : warp - NR;
    const float* row = (isA ? a : b) + (size_t)r * DD;

    float v0 = row[lane], v1 = row[lane + 32];
    __half h0 = __float2half_rn(v0);
    __half h1 = __float2half_rn(v1);
    if (isA) {
        // A side: hi only
        g_ah[(size_t)r * DD + lane]      = h0;
        g_ah[(size_t)r * DD + lane + 32] = h1;
    } else {
        // B side: hi + residual lo
        g_bh[(size_t)r * DD + lane]      = h0;
        g_bh[(size_t)r * DD + lane + 32] = h1;
        g_bl[(size_t)r * DD + lane]      = __float2half_rn(v0 - __half2float(h0));
        g_bl[(size_t)r * DD + lane + 32] = __float2half_rn(v1 - __half2float(h1));
    }

    float s = fmaf(v0, v0, v1 * v1);
    #pragma unroll
    for (int o = 16; o > 0; o >>= 1) s += __shfl_xor_sync(0xffffffffu, s, o);
    if (lane == 0) {
        if (isA) {
            float t = 2.0f / (1.0f - s);
            g_apa[r] = make_float2(s, t * t);
        } else {
            float t = 1.0f / (1.0f - s);
            g_bq[r] = make_float2(s, t * t);
        }
    }
}

// ---------------- main: 2-pass fp16-split HMMA GEMM + fused Poincare epilogue ----------------
// CTA tile 64(M: a-rows) x 128(N: b-rows), K = 64 in one shot.
// 8 warps: warp grid 2(M) x 4(N); warp tile 32x32. 3 CTAs/SM.
#define PITCH 144
#define A_TILE_BYTES (64 * PITCH)     // 9216  (A hi only)
#define B_TILE_BYTES (128 * PITCH)    // 18432 per array
#define SMEM_TOTAL (A_TILE_BYTES + 2 * B_TILE_BYTES)   // 46080

__global__ void __launch_bounds__(256, 3)
poincare_hmma_kernel(float* __restrict__ out) {
    extern __shared__ char smem[];
    char* sA  = smem;
    char* sBh = smem + A_TILE_BYTES;
    char* sBl = smem + A_TILE_BYTES + B_TILE_BYTES;

    const int tid = threadIdx.x;
    const int lane = tid & 31;
    const int wid = tid >> 5;
    const int wm = wid >> 2;
    const int wn = wid & 3;

    const int row0 = blockIdx.y * 64;
    const int col0 = blockIdx.x * 128;

    // ---- stage tiles via cp.async ----
    {
        const uint32_t sb = smem_u32(smem);
        #pragma unroll
        for (int t = 0; t < 2; t++) {
            int chunk = tid + 256 * t;          // 0..511
            int r = chunk >> 3;
            int kc = chunk & 7;
            uint32_t doff = (uint32_t)(r * PITCH + kc * 16);
            CP_ASYNC16(sb + doff, g_ah + (size_t)(row0 + r) * DD + kc * 8);
        }
        #pragma unroll
        for (int t = 0; t < 4; t++) {
            int chunk = tid + 256 * t;          // 0..1023
            int r = chunk >> 3;
            int kc = chunk & 7;
            uint32_t doff = (uint32_t)(r * PITCH + kc * 16);
            CP_ASYNC16(sb + A_TILE_BYTES + doff,
                       g_bh + (size_t)(col0 + r) * DD + kc * 8);
            CP_ASYNC16(sb + A_TILE_BYTES + B_TILE_BYTES + doff,
                       g_bl + (size_t)(col0 + r) * DD + kc * 8);
        }
        CP_COMMIT();
        CP_WAIT0();
    }
    __syncthreads();

    // ---- hoisted epilogue stats ----
    const int er = row0 + wm * 32 + (lane >> 2);
    const int ec = col0 + wn * 32 + 2 * (lane & 3);
    float2 rs[2][2];
    float2 cs[4][2];
    #pragma unroll
    for (int mf = 0; mf < 2; mf++) {
        rs[mf][0] = __ldg(&g_apa[er + mf * 16]);
        rs[mf][1] = __ldg(&g_apa[er + mf * 16 + 8]);
    }
    #pragma unroll
    for (int nf = 0; nf < 4; nf++) {
        cs[nf][0] = __ldg(&g_bq[ec + nf * 8]);
        cs[nf][1] = __ldg(&g_bq[ec + nf * 8 + 1]);
    }

    float acc[2][4][4];
    #pragma unroll
    for (int i = 0; i < 2; i++)
        #pragma unroll
        for (int j = 0; j < 4; j++)
            #pragma unroll
            for (int q = 0; q < 4; q++) acc[i][j][q] = 0.0f;

    const uint32_t a_row  = (uint32_t)(wm * 32 + (lane & 15));
    const uint32_t a_koff = (uint32_t)((lane >> 4) * 16);
    const uint32_t b_row  = (uint32_t)(wn * 32 + ((lane & 16) >> 1) + (lane & 7));
    const uint32_t b_koff = (uint32_t)(((lane >> 3) & 1) * 16);

    const uint32_t uA  = smem_u32(sA);
    const uint32_t uBh = smem_u32(sBh);
    const uint32_t uBl = smem_u32(sBl);

    #pragma unroll
    for (int ks = 0; ks < 4; ks++) {
        const uint32_t kb = (uint32_t)(ks * 32);
        uint32_t Ah[2][4];
        #pragma unroll
        for (int mf = 0; mf < 2; mf++) {
            uint32_t off = (a_row + mf * 16) * PITCH + kb + a_koff;
            LDSM4(Ah[mf], uA + off);
        }
        uint32_t Bh[2][4], Bl[2][4];
        #pragma unroll
        for (int nh = 0; nh < 2; nh++) {
            uint32_t off = (b_row + nh * 16) * PITCH + kb + b_koff;
            LDSM4(Bh[nh], uBh + off);
            LDSM4(Bl[nh], uBl + off);
        }
        #pragma unroll
        for (int nf = 0; nf < 4; nf++) {
            uint32_t bh0 = Bh[nf >> 1][(nf & 1) * 2], bh1 = Bh[nf >> 1][(nf & 1) * 2 + 1];
            uint32_t bl0 = Bl[nf >> 1][(nf & 1) * 2], bl1 = Bl[nf >> 1][(nf & 1) * 2 + 1];
            #pragma unroll
            for (int mf = 0; mf < 2; mf++) {
                MMA16816(acc[mf][nf], Ah[mf], bh0, bh1);   // ah*bh
                MMA16816(acc[mf][nf], Ah[mf], bl0, bl1);   // ah*bl
            }
        }
    }

    // ---- fused Poincare epilogue (z-form, squared stats) ----
    // z = y^2 = sq * (2/(1-a2))^2 * (1/(1-b2))^2 ; y = sqrt(z)
    // res = log(1 + y + sqrt(z + 2y))
    #pragma unroll
    for (int mf = 0; mf < 2; mf++) {
        #pragma unroll
        for (int nf = 0; nf < 4; nf++) {
            float res[4];
            #pragma unroll
            for (int q = 0; q < 4; q++) {
                float2 ra = rs[mf][q >> 1];
                float2 cb = cs[nf][q & 1];
                float sq = fmaf(-2.0f, acc[mf][nf][q], ra.x + cb.x);
                sq = fmaxf(sq, 0.0f);
                float z  = (sq * ra.y) * cb.y;
                float y  = fast_sqrt(z);
                float tt = fmaf(2.0f, y, z);
                res[q] = __logf(1.0f + y + fast_sqrt(tt));
            }
            size_t r0 = (size_t)(er + mf * 16) * MC + (ec + nf * 8);
            *reinterpret_cast<float2*>(out + r0)          = make_float2(res[0], res[1]);
            *reinterpret_cast<float2*>(out + r0 + 8 * MC) = make_float2(res[2], res[3]);
        }
    }
}

extern "C" void kernel_launch(void* const* d_in, const int* in_sizes, int n_in,
                              void* d_out, int out_size) {
    const float* a = (const float*)d_in[0];
    const float* b = (const float*)d_in[1];
    float* out = (float*)d_out;

    cudaFuncSetAttribute(poincare_hmma_kernel,
                         cudaFuncAttributeMaxDynamicSharedMemorySize, SMEM_TOTAL);

    poincare_prep_kernel<<<(NR + MC) / 8, 256>>>(a, b);
    dim3 grid(MC / 128, NR / 64);
    poincare_hmma_kernel<<<grid, 256, SMEM_TOTAL>>>(out);
}

// round 12
// speedup vs baseline: 1.5428x; 1.2371x over previous
#include <cuda_runtime.h>
#include <cuda_fp16.h>
#include <cstdint>

#define NR 8192
#define MC 8192
#define DD 64

// ---------------- device-global staging (no allocation allowed) ----------------
__device__ __align__(16) __half g_ah[NR * DD];   // A: fp16 (single-pass)
__device__ __align__(16) __half g_bh[MC * DD];   // B: fp16 (single-pass)
// stats: x = |p|^2 (fp32 from raw data) ; y = SQUARED reciprocal term
__device__ float2 g_apa[NR];
__device__ float2 g_bq[MC];

// ---------------- helpers ----------------
__device__ __forceinline__ float fast_sqrt(float x) {
    float r; asm("sqrt.approx.f32 %0, %1;" : "=f"(r) : "f"(x)); return r;
}
__device__ __forceinline__ uint32_t smem_u32(const void* p) {
    uint32_t a;
    asm("{ .reg .u64 t; cvta.to.shared.u64 t, %1; cvt.u32.u64 %0, t; }" : "=r"(a) : "l"(p));
    return a;
}
#define CP_ASYNC16(dst, src) \
    asm volatile("cp.async.cg.shared.global [%0], [%1], 16;" :: "r"(dst), "l"(src) : "memory")
#define CP_COMMIT() asm volatile("cp.async.commit_group;" ::: "memory")
#define CP_WAIT0()  asm volatile("cp.async.wait_group 0;" ::: "memory")

#define LDSM4(R, a) \
    asm volatile("ldmatrix.sync.aligned.m8n8.x4.shared.b16 {%0,%1,%2,%3}, [%4];" \
        : "=r"((R)[0]), "=r"((R)[1]), "=r"((R)[2]), "=r"((R)[3]) : "r"(a))

#define MMA16816(d, a, b0, b1) \
    asm volatile("mma.sync.aligned.m16n8k16.row.col.f32.f16.f16.f32 " \
        "{%0,%1,%2,%3}, {%4,%5,%6,%7}, {%8,%9}, {%0,%1,%2,%3};" \
        : "+f"((d)[0]), "+f"((d)[1]), "+f"((d)[2]), "+f"((d)[3]) \
        : "r"((a)[0]), "r"((a)[1]), "r"((a)[2]), "r"((a)[3]), "r"(b0), "r"(b1))

// ---------------- prep: norms + SQUARED reciprocal terms + fp16 convert ----------------
__global__ void poincare_prep_kernel(const float* __restrict__ a,
                                     const float* __restrict__ b) {
    int warp = (blockIdx.x * blockDim.x + threadIdx.x) >> 5;
    int lane = threadIdx.x & 31;
    bool isA = warp < NR;
    int r = isA ? warp : warp - NR;
    const float* row = (isA ? a : b) + (size_t)r * DD;

    float v0 = row[lane], v1 = row[lane + 32];
    __half h0 = __float2half_rn(v0);
    __half h1 = __float2half_rn(v1);
    __half* dst = (isA ? g_ah : g_bh) + (size_t)r * DD;
    dst[lane]      = h0;
    dst[lane + 32] = h1;

    float s = fmaf(v0, v0, v1 * v1);
    #pragma unroll
    for (int o = 16; o > 0; o >>= 1) s += __shfl_xor_sync(0xffffffffu, s, o);
    if (lane == 0) {
        if (isA) {
            float t = 2.0f / (1.0f - s);
            g_apa[r] = make_float2(s, t * t);
        } else {
            float t = 1.0f / (1.0f - s);
            g_bq[r] = make_float2(s, t * t);
        }
    }
}

// ---------------- main: single-pass fp16 HMMA GEMM + fused Poincare epilogue ----------------
// CTA tile 64(M: a-rows) x 128(N: b-rows), K = 64 in one shot.
// 8 warps: warp grid 2(M) x 4(N); warp tile 32x32. 3 CTAs/SM.
#define PITCH 144
#define A_TILE_BYTES (64 * PITCH)     // 9216
#define B_TILE_BYTES (128 * PITCH)    // 18432
#define SMEM_TOTAL (A_TILE_BYTES + B_TILE_BYTES)   // 27648

__global__ void __launch_bounds__(256, 3)
poincare_hmma_kernel(float* __restrict__ out) {
    extern __shared__ char smem[];
    char* sA = smem;
    char* sB = smem + A_TILE_BYTES;

    const int tid = threadIdx.x;
    const int lane = tid & 31;
    const int wid = tid >> 5;
    const int wm = wid >> 2;
    const int wn = wid & 3;

    const int row0 = blockIdx.y * 64;
    const int col0 = blockIdx.x * 128;

    // ---- stage tiles via cp.async ----
    {
        const uint32_t sb = smem_u32(smem);
        #pragma unroll
        for (int t = 0; t < 2; t++) {
            int chunk = tid + 256 * t;          // 0..511
            int r = chunk >> 3;
            int kc = chunk & 7;
            uint32_t doff = (uint32_t)(r * PITCH + kc * 16);
            CP_ASYNC16(sb + doff, g_ah + (size_t)(row0 + r) * DD + kc * 8);
        }
        #pragma unroll
        for (int t = 0; t < 4; t++) {
            int chunk = tid + 256 * t;          // 0..1023
            int r = chunk >> 3;
            int kc = chunk & 7;
            uint32_t doff = (uint32_t)(r * PITCH + kc * 16);
            CP_ASYNC16(sb + A_TILE_BYTES + doff,
                       g_bh + (size_t)(col0 + r) * DD + kc * 8);
        }
        CP_COMMIT();
        CP_WAIT0();
    }
    __syncthreads();

    // ---- hoisted epilogue stats ----
    const int er = row0 + wm * 32 + (lane >> 2);
    const int ec = col0 + wn * 32 + 2 * (lane & 3);
    float2 rs[2][2];
    float2 cs[4][2];
    #pragma unroll
    for (int mf = 0; mf < 2; mf++) {
        rs[mf][0] = __ldg(&g_apa[er + mf * 16]);
        rs[mf][1] = __ldg(&g_apa[er + mf * 16 + 8]);
    }
    #pragma unroll
    for (int nf = 0; nf < 4; nf++) {
        cs[nf][0] = __ldg(&g_bq[ec + nf * 8]);
        cs[nf][1] = __ldg(&g_bq[ec + nf * 8 + 1]);
    }

    float acc[2][4][4];
    #pragma unroll
    for (int i = 0; i < 2; i++)
        #pragma unroll
        for (int j = 0; j < 4; j++)
            #pragma unroll
            for (int q = 0; q < 4; q++) acc[i][j][q] = 0.0f;

    const uint32_t a_row  = (uint32_t)(wm * 32 + (lane & 15));
    const uint32_t a_koff = (uint32_t)((lane >> 4) * 16);
    const uint32_t b_row  = (uint32_t)(wn * 32 + ((lane & 16) >> 1) + (lane & 7));
    const uint32_t b_koff = (uint32_t)(((lane >> 3) & 1) * 16);

    const uint32_t uA = smem_u32(sA);
    const uint32_t uB = smem_u32(sB);

    #pragma unroll
    for (int ks = 0; ks < 4; ks++) {
        const uint32_t kb = (uint32_t)(ks * 32);
        uint32_t Ah[2][4];
        #pragma unroll
        for (int mf = 0; mf < 2; mf++) {
            uint32_t off = (a_row + mf * 16) * PITCH + kb + a_koff;
            LDSM4(Ah[mf], uA + off);
        }
        uint32_t Bh[2][4];
        #pragma unroll
        for (int nh = 0; nh < 2; nh++) {
            uint32_t off = (b_row + nh * 16) * PITCH + kb + b_koff;
            LDSM4(Bh[nh], uB + off);
        }
        #pragma unroll
        for (int nf = 0; nf < 4; nf++) {
            uint32_t b0 = Bh[nf >> 1][(nf & 1) * 2], b1 = Bh[nf >> 1][(nf & 1) * 2 + 1];
            #pragma unroll
            for (int mf = 0; mf < 2; mf++)
                MMA16816(acc[mf][nf], Ah[mf], b0, b1);
        }
    }

    // ---- fused Poincare epilogue (z-form, squared stats) ----
    // z = y^2 = sq * (2/(1-a2))^2 * (1/(1-b2))^2 ; y = sqrt(z)
    // res = log(1 + y + sqrt(z + 2y))
    #pragma unroll
    for (int mf = 0; mf < 2; mf++) {
        #pragma unroll
        for (int nf = 0; nf < 4; nf++) {
            float res[4];
            #pragma unroll
            for (int q = 0; q < 4; q++) {
                float2 ra = rs[mf][q >> 1];
                float2 cb = cs[nf][q & 1];
                float sq = fmaf(-2.0f, acc[mf][nf][q], ra.x + cb.x);
                sq = fmaxf(sq, 0.0f);
                float z  = (sq * ra.y) * cb.y;
                float y  = fast_sqrt(z);
                float tt = fmaf(2.0f, y, z);
                res[q] = __logf(1.0f + y + fast_sqrt(tt));
            }
            size_t r0 = (size_t)(er + mf * 16) * MC + (ec + nf * 8);
            *reinterpret_cast<float2*>(out + r0)          = make_float2(res[0], res[1]);
            *reinterpret_cast<float2*>(out + r0 + 8 * MC) = make_float2(res[2], res[3]);
        }
    }
}

extern "C" void kernel_launch(void* const* d_in, const int* in_sizes, int n_in,
                              void* d_out, int out_size) {
    const float* a = (const float*)d_in[0];
    const float* b = (const float*)d_in[1];
    float* out = (float*)d_out;

    cudaFuncSetAttribute(poincare_hmma_kernel,
                         cudaFuncAttributeMaxDynamicSharedMemorySize, SMEM_TOTAL);

    poincare_prep_kernel<<<(NR + MC) / 8, 256>>>(a, b);
    dim3 grid(MC / 128, NR / 64);
    poincare_hmma_kernel<<<grid, 256, SMEM_TOTAL>>>(out);
}